// round 16
// baseline (speedup 1.0000x reference)
#include <cuda_runtime.h>
#include <cstdint>
#include <cstddef>

#define NN 50000
#define NE 800000
#define SCAN_T 1024
#define SCAN_B ((NN + SCAN_T - 1) / SCAN_T)   // 49

// ---------------- static device scratch ----------------
__device__ float d_dinv[NN];
__device__ int   d_counts[NN];
__device__ int   d_scanned[NN];
__device__ int   d_scanblk[SCAN_B];
__device__ int   d_rowptr[NN + 1];
__device__ int   d_epos[NE];       // per-edge slot within its dst row
__device__ int   d_csr_src[NE];
__device__ float d_csr_w[NE];      // raw edge weight (un-normalized)
__device__ float d_h1[NN * 64];
__device__ float d_z[NN];
__device__ float d_w2f[512];   // fc2_W @ fcf_W[0:64]
__device__ float d_vg[64];     // gcn2_W @ fcf_W[64:128]
__device__ float d_cmlp;       // fc2_b . fcf_W[0:64]
__device__ float d_cgnn;       // gcn2_b . fcf_W[64:128] + fcf_b
__device__ float d_w1f[8 * 8 * 4096];   // W1 tf32, fragment-major [bcol][kt][4096]
__device__ float d_g1f[8 * 2048];       // g1W tf32, fragment-major [kt][2048]

// ---------------- tf32 helper ----------------
__device__ __forceinline__ uint32_t f2tf32(float f) {
    uint32_t u;
    asm("cvt.rna.tf32.f32 %0, %1;" : "=r"(u) : "f"(f));
    return u;
}

// ---------------- precompute collapsed vectors ----------------
__global__ void prep_vecs(const float* __restrict__ W2, const float* __restrict__ g2W,
                          const float* __restrict__ b2, const float* __restrict__ g2b,
                          const float* __restrict__ Wf, const float* __restrict__ fb) {
    int t = threadIdx.x;   // 512 threads
    float s = 0.f;
#pragma unroll 8
    for (int c = 0; c < 64; c++) s += W2[t * 64 + c] * Wf[c];
    d_w2f[t] = s;
    if (t < 64) {
        float s2 = 0.f;
#pragma unroll 8
        for (int c = 0; c < 64; c++) s2 += g2W[t * 64 + c] * Wf[64 + c];
        d_vg[t] = s2;
    }
    if (t == 0) {
        float cm = 0.f, cg = 0.f;
        for (int c = 0; c < 64; c++) { cm += b2[c] * Wf[c]; cg += g2b[c] * Wf[64 + c]; }
        d_cmlp = cm;
        d_cgnn = cg + fb[0];
    }
}

// ---------------- fragment-major weight packing (B operands only) ----------------
__global__ void prep_w1f(const float* __restrict__ W1) {
    int idx = blockIdx.x * blockDim.x + threadIdx.x;
    if (idx >= 8 * 8 * 4096) return;
    int tile = idx >> 12, w = idx & 4095;
    int bcol = tile >> 3, kt = tile & 7;
    int q = w >> 7, lane = (w >> 2) & 31, j = w & 3;
    int ks = q >> 3, wn = (q >> 2) & 1, ntp = q & 3;
    int g = lane >> 2, t = lane & 3, ntodd = j >> 1, r = j & 1;
    int k = kt * 32 + ks * 8 + t + r * 4;
    int n = bcol * 128 + (wn * 8 + ntp * 2 + ntodd) * 8 + g;
    d_w1f[idx] = __uint_as_float(f2tf32(W1[(size_t)k * 512 + n]));
}

__global__ void prep_g1f(const float* __restrict__ B) {
    int idx = blockIdx.x * blockDim.x + threadIdx.x;
    if (idx >= 8 * 2048) return;
    int kt = idx >> 11, w = idx & 2047;
    int q = w >> 7, lane = (w >> 2) & 31, j = w & 3;
    int ks = q >> 2, ntp2 = q & 3;
    int g = lane >> 2, t = lane & 3, ntodd = j >> 1, r = j & 1;
    int k = kt * 32 + ks * 8 + t + r * 4;
    int n = (ntp2 * 2 + ntodd) * 8 + g;
    d_g1f[idx] = __uint_as_float(f2tf32(B[(size_t)k * 64 + n]));
}

// ---------------- graph preprocessing ----------------
// count pass also records each edge's slot within its destination row
__global__ void edge_count_pos(const int* __restrict__ dst) {
    int e = blockIdx.x * blockDim.x + threadIdx.x;
    if (e < NE) d_epos[e] = atomicAdd(&d_counts[dst[e]], 1);
}

__global__ void scan_block() {
    __shared__ int s[SCAN_T];
    int tid = threadIdx.x;
    int i = blockIdx.x * SCAN_T + tid;
    int v = (i < NN) ? d_counts[i] : 0;
    s[tid] = v;
    __syncthreads();
#pragma unroll
    for (int off = 1; off < SCAN_T; off <<= 1) {
        int t = (tid >= off) ? s[tid - off] : 0;
        __syncthreads();
        s[tid] += t;
        __syncthreads();
    }
    if (i < NN) d_scanned[i] = s[tid];
    if (tid == SCAN_T - 1) d_scanblk[blockIdx.x] = s[tid];
}

__global__ void scan_top() {
    __shared__ int s[64];
    int tid = threadIdx.x;
    int v = (tid < SCAN_B) ? d_scanblk[tid] : 0;
    s[tid] = v;
    __syncthreads();
#pragma unroll
    for (int off = 1; off < 64; off <<= 1) {
        int t = (tid >= off) ? s[tid - off] : 0;
        __syncthreads();
        s[tid] += t;
        __syncthreads();
    }
    if (tid < SCAN_B) d_scanblk[tid] = (tid == 0) ? 0 : s[tid - 1];
}

__global__ void finalize_rowptr() {
    int i = blockIdx.x * blockDim.x + threadIdx.x;
    if (i < NN) {
        d_rowptr[i + 1] = d_scanned[i] + d_scanblk[i >> 10];
        if (i == 0) d_rowptr[0] = 0;
    }
}

// atomic-free scatter: slot = rowptr[dst] + epos[e]
__global__ void fill_csr(const int* __restrict__ src, const int* __restrict__ dst,
                         const float* __restrict__ ew) {
    int e = blockIdx.x * blockDim.x + threadIdx.x;
    if (e < NE) {
        int pos = d_rowptr[dst[e]] + d_epos[e];
        d_csr_src[pos] = src[e];
        d_csr_w[pos] = ew[e];
    }
}

__global__ void deg_dinv() {
    int gw = (blockIdx.x * blockDim.x + threadIdx.x) >> 5;
    int lane = threadIdx.x & 31;
    if (gw >= NN) return;
    int beg = d_rowptr[gw];
    int end = d_rowptr[gw + 1];
    float s = 0.f;
    for (int j = beg + lane; j < end; j += 32) s += d_csr_w[j];
#pragma unroll
    for (int off = 16; off > 0; off >>= 1)
        s += __shfl_down_sync(0xFFFFFFFFu, s, off);
    if (lane == 0) d_dinv[gw] = rsqrtf(s + 1.0f);
}

// ---------------- GCN aggregation 1 + relu + z = g . vg ----------------
__global__ void gcn_agg1_z(const float* __restrict__ h, const float* __restrict__ bias,
                           float* __restrict__ z) {
    int gw = (blockIdx.x * blockDim.x + threadIdx.x) >> 5;
    int lane = threadIdx.x & 31;
    if (gw >= NN) return;
    int i = gw;
    float di = d_dinv[i];
    float a0 = di * h[(size_t)i * 64 + lane];
    float a1 = di * h[(size_t)i * 64 + 32 + lane];
    int beg = d_rowptr[i];
    int end = d_rowptr[i + 1];
    for (int jb = beg; jb < end; jb += 32) {
        int n = end - jb; if (n > 32) n = 32;
        int sj = 0; float wj = 0.f;
        if (lane < n) {
            sj = d_csr_src[jb + lane];
            wj = d_csr_w[jb + lane] * d_dinv[sj];
        }
        int k = 0;
        for (; k + 2 <= n; k += 2) {
            int s0 = __shfl_sync(0xFFFFFFFFu, sj, k);
            float w0 = __shfl_sync(0xFFFFFFFFu, wj, k);
            int s1 = __shfl_sync(0xFFFFFFFFu, sj, k + 1);
            float w1 = __shfl_sync(0xFFFFFFFFu, wj, k + 1);
            float v00 = h[(size_t)s0 * 64 + lane];
            float v01 = h[(size_t)s0 * 64 + 32 + lane];
            float v10 = h[(size_t)s1 * 64 + lane];
            float v11 = h[(size_t)s1 * 64 + 32 + lane];
            a0 += w0 * v00 + w1 * v10;
            a1 += w0 * v01 + w1 * v11;
        }
        if (k < n) {
            int s = __shfl_sync(0xFFFFFFFFu, sj, k);
            float w = __shfl_sync(0xFFFFFFFFu, wj, k);
            a0 += w * h[(size_t)s * 64 + lane];
            a1 += w * h[(size_t)s * 64 + 32 + lane];
        }
    }
    a0 = fmaxf(a0 * di + bias[lane], 0.0f);
    a1 = fmaxf(a1 * di + bias[32 + lane], 0.0f);
    float zi = a0 * d_vg[lane] + a1 * d_vg[32 + lane];
#pragma unroll
    for (int off = 16; off > 0; off >>= 1)
        zi += __shfl_down_sync(0xFFFFFFFFu, zi, off);
    if (lane == 0) z[i] = zi;
}

// ---------------- scalar aggregation 2, accumulate into out ----------------
__global__ void gcn_agg2_out(const float* __restrict__ z, float* __restrict__ out) {
    int gw = (blockIdx.x * blockDim.x + threadIdx.x) >> 5;
    int lane = threadIdx.x & 31;
    if (gw >= NN) return;
    int i = gw;
    float di = d_dinv[i];
    float acc = (lane == 0) ? di * z[i] : 0.0f;
    int beg = d_rowptr[i];
    int end = d_rowptr[i + 1];
    for (int j = beg + lane; j < end; j += 32) {
        int s = d_csr_src[j];
        acc += d_csr_w[j] * d_dinv[s] * z[s];
    }
#pragma unroll
    for (int off = 16; off > 0; off >>= 1)
        acc += __shfl_down_sync(0xFFFFFFFFu, acc, off);
    if (lane == 0) atomicAdd(&out[i], acc * di + d_cmlp + d_cgnn);
}

// ---------------- mma / cp.async helpers ----------------
__device__ __forceinline__ void mma_tf32(float c[4], uint4 a, uint2 b) {
    asm volatile(
        "mma.sync.aligned.m16n8k8.row.col.f32.tf32.tf32.f32 "
        "{%0,%1,%2,%3},{%4,%5,%6,%7},{%8,%9},{%0,%1,%2,%3};\n"
        : "+f"(c[0]), "+f"(c[1]), "+f"(c[2]), "+f"(c[3])
        : "r"(a.x), "r"(a.y), "r"(a.z), "r"(a.w), "r"(b.x), "r"(b.y));
}

__device__ __forceinline__ uint32_t smem_u32(const void* p) {
    return (uint32_t)__cvta_generic_to_shared(p);
}
__device__ __forceinline__ void cp16(uint32_t dst, const void* src) {
    asm volatile("cp.async.cg.shared.global [%0], [%1], 16;" :: "r"(dst), "l"(src));
}
#define CP_COMMIT() asm volatile("cp.async.commit_group;" ::: "memory")
#define CP_WAIT(n)  asm volatile("cp.async.wait_group %0;" :: "n"(n) : "memory")

// A smem: row-major + XOR swizzle, word = row*32 + (k ^ ((row&7)<<2))
// B smem: fragment-major (packed offline), one LDS.128 per nt-pair.

// ---------------- MLP GEMM: out[row] += relu(uf@W1+b1)[row,:] . w2f ----------------
#define MLP_SMEM_BYTES ((3 * 4096 + 3 * 4096 + 128) * 4)

__global__ __launch_bounds__(256, 2) void mlp_gemm(
    int M, const float* __restrict__ A,
    const float* __restrict__ b1, float* __restrict__ out) {

    extern __shared__ float sm[];
    float* sA = sm;                // 3 x 4096
    float* sB = sm + 3 * 4096;     // 3 x 4096
    float* sRed = sm + 6 * 4096;   // 128

    const int tid = threadIdx.x, brow = blockIdx.y, bcol = blockIdx.x;
    const int w = tid >> 5, lane = tid & 31, wm = w & 3, wn = w >> 2;
    const int g = lane >> 2, t = lane & 3;
    const int swA = g << 2;
    if (tid < 128) sRed[tid] = 0.f;

    const uint32_t sAu = smem_u32(sA), sBu = smem_u32(sB);
    const float* w1tile = d_w1f + (size_t)bcol * 8 * 4096;

    auto issue = [&](int kt, int s) {
#pragma unroll
        for (int i = 0; i < 4; i++) {
            int idx = tid + i * 256;
            int row = idx >> 3, c = idx & 7;
            int grow = brow * 128 + row; if (grow >= M) grow = M - 1;
            uint32_t dst = sAu + (uint32_t)(s * 4096 + row * 32 + ((c ^ (row & 7)) << 2)) * 4u;
            cp16(dst, &A[(size_t)grow * 256 + kt * 32 + c * 4]);
        }
#pragma unroll
        for (int i = 0; i < 4; i++) {
            int widx = (tid + i * 256) * 4;
            cp16(sBu + (uint32_t)(s * 4096 + widx) * 4u, &w1tile[kt * 4096 + widx]);
        }
        CP_COMMIT();
    };

    float acc[2][8][4] = {};

    issue(0, 0);
    issue(1, 1);
#pragma unroll
    for (int kt = 0; kt < 8; kt++) {
        if (kt == 7) { CP_WAIT(0); } else { CP_WAIT(1); }
        __syncthreads();
        const float* bA = sA + (kt % 3) * 4096;
        const uint4* bB4 = (const uint4*)(sB + (kt % 3) * 4096);
#pragma unroll
        for (int ks = 0; ks < 4; ks++) {
            const int kb = ks * 8;
            uint4 a[2];
#pragma unroll
            for (int mt = 0; mt < 2; mt++) {
                int r0 = wm * 32 + mt * 16 + g;
                int r1 = r0 + 8;
                a[mt].x = f2tf32(bA[r0 * 32 + ((kb + t) ^ swA)]);
                a[mt].y = f2tf32(bA[r1 * 32 + ((kb + t) ^ swA)]);
                a[mt].z = f2tf32(bA[r0 * 32 + ((kb + t + 4) ^ swA)]);
                a[mt].w = f2tf32(bA[r1 * 32 + ((kb + t + 4) ^ swA)]);
            }
#pragma unroll
            for (int ntp = 0; ntp < 4; ntp++) {
                uint4 bb = bB4[(ks * 8 + wn * 4 + ntp) * 32 + lane];
                uint2 b0 = make_uint2(bb.x, bb.y);
                uint2 b1v = make_uint2(bb.z, bb.w);
                mma_tf32(acc[0][ntp * 2], a[0], b0);
                mma_tf32(acc[1][ntp * 2], a[1], b0);
                mma_tf32(acc[0][ntp * 2 + 1], a[0], b1v);
                mma_tf32(acc[1][ntp * 2 + 1], a[1], b1v);
            }
        }
        if (kt < 6) issue(kt + 2, (kt + 2) % 3);
    }

    // epilogue: relu + dot with w2f
    float p[2][2] = {{0.f, 0.f}, {0.f, 0.f}};
#pragma unroll
    for (int nt = 0; nt < 8; nt++) {
        int gcol = bcol * 128 + wn * 64 + nt * 8 + t * 2;
        float bb0 = b1[gcol], bb1 = b1[gcol + 1];
        float w0 = d_w2f[gcol], w1 = d_w2f[gcol + 1];
#pragma unroll
        for (int mt = 0; mt < 2; mt++) {
            p[mt][0] += fmaxf(acc[mt][nt][0] + bb0, 0.f) * w0 + fmaxf(acc[mt][nt][1] + bb1, 0.f) * w1;
            p[mt][1] += fmaxf(acc[mt][nt][2] + bb0, 0.f) * w0 + fmaxf(acc[mt][nt][3] + bb1, 0.f) * w1;
        }
    }
#pragma unroll
    for (int off = 1; off <= 2; off <<= 1) {
        p[0][0] += __shfl_xor_sync(0xFFFFFFFFu, p[0][0], off);
        p[0][1] += __shfl_xor_sync(0xFFFFFFFFu, p[0][1], off);
        p[1][0] += __shfl_xor_sync(0xFFFFFFFFu, p[1][0], off);
        p[1][1] += __shfl_xor_sync(0xFFFFFFFFu, p[1][1], off);
    }
    if (t == 0) {
#pragma unroll
        for (int mt = 0; mt < 2; mt++) {
            int r0 = wm * 32 + mt * 16 + g;
            atomicAdd(&sRed[r0], p[mt][0]);
            atomicAdd(&sRed[r0 + 8], p[mt][1]);
        }
    }
    __syncthreads();
    if (tid < 128) {
        int grow = brow * 128 + tid;
        if (grow < M) atomicAdd(&out[grow], sRed[tid]);
    }
}

// ---------------- GCN1 transform: h1 = x @ g1W ----------------
#define G1_SMEM_BYTES ((3 * 4096 + 3 * 2048) * 4)

__global__ __launch_bounds__(128, 2) void gcn1_gemm(
    int M, const float* __restrict__ A, float* __restrict__ C) {

    extern __shared__ float sm[];
    float* sA = sm;
    float* sB = sm + 3 * 4096;

    const int tid = threadIdx.x, brow = blockIdx.x;
    const int wm = tid >> 5, lane = tid & 31;
    const int g = lane >> 2, t = lane & 3;
    const int swA = g << 2;

    const uint32_t sAu = smem_u32(sA), sBu = smem_u32(sB);

    auto issue = [&](int kt, int s) {
#pragma unroll
        for (int i = 0; i < 8; i++) {
            int idx = tid + i * 128;
            int row = idx >> 3, c = idx & 7;
            int grow = brow * 128 + row; if (grow >= M) grow = M - 1;
            uint32_t dst = sAu + (uint32_t)(s * 4096 + row * 32 + ((c ^ (row & 7)) << 2)) * 4u;
            cp16(dst, &A[(size_t)grow * 256 + kt * 32 + c * 4]);
        }
#pragma unroll
        for (int i = 0; i < 4; i++) {
            int widx = (tid + i * 128) * 4;
            cp16(sBu + (uint32_t)(s * 2048 + widx) * 4u, &d_g1f[kt * 2048 + widx]);
        }
        CP_COMMIT();
    };

    float acc[2][8][4] = {};

    issue(0, 0);
    issue(1, 1);
#pragma unroll
    for (int kt = 0; kt < 8; kt++) {
        if (kt == 7) { CP_WAIT(0); } else { CP_WAIT(1); }
        __syncthreads();
        const float* bA = sA + (kt % 3) * 4096;
        const uint4* bB4 = (const uint4*)(sB + (kt % 3) * 2048);
#pragma unroll
        for (int ks = 0; ks < 4; ks++) {
            const int kb = ks * 8;
            uint4 a[2];
#pragma unroll
            for (int mt = 0; mt < 2; mt++) {
                int r0 = wm * 32 + mt * 16 + g;
                int r1 = r0 + 8;
                a[mt].x = f2tf32(bA[r0 * 32 + ((kb + t) ^ swA)]);
                a[mt].y = f2tf32(bA[r1 * 32 + ((kb + t) ^ swA)]);
                a[mt].z = f2tf32(bA[r0 * 32 + ((kb + t + 4) ^ swA)]);
                a[mt].w = f2tf32(bA[r1 * 32 + ((kb + t + 4) ^ swA)]);
            }
#pragma unroll
            for (int ntp2 = 0; ntp2 < 4; ntp2++) {
                uint4 bb = bB4[(ks * 4 + ntp2) * 32 + lane];
                uint2 b0 = make_uint2(bb.x, bb.y);
                uint2 b1v = make_uint2(bb.z, bb.w);
                mma_tf32(acc[0][ntp2 * 2], a[0], b0);
                mma_tf32(acc[1][ntp2 * 2], a[1], b0);
                mma_tf32(acc[0][ntp2 * 2 + 1], a[0], b1v);
                mma_tf32(acc[1][ntp2 * 2 + 1], a[1], b1v);
            }
        }
        if (kt < 6) issue(kt + 2, (kt + 2) % 3);
    }

#pragma unroll
    for (int mt = 0; mt < 2; mt++) {
#pragma unroll
        for (int nt = 0; nt < 8; nt++) {
            int gcol = nt * 8 + t * 2;
            int grow0 = brow * 128 + wm * 32 + mt * 16 + g;
            if (grow0 < M)
                *(float2*)&C[(size_t)grow0 * 64 + gcol] = make_float2(acc[mt][nt][0], acc[mt][nt][1]);
            if (grow0 + 8 < M)
                *(float2*)&C[(size_t)(grow0 + 8) * 64 + gcol] = make_float2(acc[mt][nt][2], acc[mt][nt][3]);
        }
    }
}

// ---------------- launch ----------------
extern "C" void kernel_launch(void* const* d_in, const int* in_sizes, int n_in,
                              void* d_out, int out_size) {
    const float* x     = (const float*)d_in[0];
    const int*   ei    = (const int*)d_in[1];
    const float* ea    = (const float*)d_in[2];
    const float* uf    = (const float*)d_in[3];
    const float* g1W   = (const float*)d_in[4];
    const float* g1b   = (const float*)d_in[5];
    const float* g2W   = (const float*)d_in[6];
    const float* g2b   = (const float*)d_in[7];
    const float* fc1W  = (const float*)d_in[8];
    const float* fc1b  = (const float*)d_in[9];
    const float* fc2W  = (const float*)d_in[10];
    const float* fc2b  = (const float*)d_in[11];
    const float* fcfW  = (const float*)d_in[12];
    const float* fcfb  = (const float*)d_in[13];
    float* out = (float*)d_out;

    const int* src = ei;
    const int* dst = ei + NE;

    void* p;
    cudaGetSymbolAddress(&p, d_h1);     float* h1     = (float*)p;
    cudaGetSymbolAddress(&p, d_z);      float* z      = (float*)p;
    cudaGetSymbolAddress(&p, d_counts); int*   counts = (int*)p;

    const int NB_NODE = (NN + 255) / 256;
    const int NB_EDGE = (NE + 255) / 256;
    const int NB_WARP = (NN * 32 + 255) / 256;
    const int MB = (NN + 127) / 128;   // 391

    static cudaStream_t sMlp = nullptr, sGnn = nullptr;
    static cudaEvent_t evFork = nullptr, evMlp = nullptr, evGemm1 = nullptr,
                       evPrep = nullptr, evOut = nullptr;
    static bool inited = false;
    if (!inited) {
        cudaStreamCreateWithFlags(&sMlp, cudaStreamNonBlocking);
        cudaStreamCreateWithFlags(&sGnn, cudaStreamNonBlocking);
        cudaEventCreateWithFlags(&evFork, cudaEventDisableTiming);
        cudaEventCreateWithFlags(&evMlp, cudaEventDisableTiming);
        cudaEventCreateWithFlags(&evGemm1, cudaEventDisableTiming);
        cudaEventCreateWithFlags(&evPrep, cudaEventDisableTiming);
        cudaEventCreateWithFlags(&evOut, cudaEventDisableTiming);
        cudaFuncSetAttribute(mlp_gemm, cudaFuncAttributeMaxDynamicSharedMemorySize,
                             MLP_SMEM_BYTES);
        cudaFuncSetAttribute(gcn1_gemm, cudaFuncAttributeMaxDynamicSharedMemorySize,
                             G1_SMEM_BYTES);
        inited = true;
    }

    cudaEventRecord(evFork, 0);
    cudaStreamWaitEvent(sGnn, evFork, 0);
    cudaStreamWaitEvent(sMlp, evFork, 0);

    // out accumulator: zero; both branches atomicAdd into it
    cudaMemsetAsync(out, 0, NN * sizeof(float), 0);
    cudaEventRecord(evOut, 0);
    cudaStreamWaitEvent(sMlp, evOut, 0);

    // MLP branch on sMlp (independent of everything else)
    prep_vecs<<<1, 512, 0, sMlp>>>(fc2W, g2W, fc2b, g2b, fcfW, fcfb);
    cudaEventRecord(evPrep, sMlp);
    prep_w1f<<<(8 * 8 * 4096 + 255) / 256, 256, 0, sMlp>>>(fc1W);
    mlp_gemm<<<dim3(4, MB), 256, MLP_SMEM_BYTES, sMlp>>>(NN, uf, fc1b, out);
    cudaEventRecord(evMlp, sMlp);

    // GNN transform on sGnn
    prep_g1f<<<(8 * 2048 + 255) / 256, 256, 0, sGnn>>>(g1W);
    gcn1_gemm<<<MB, 128, G1_SMEM_BYTES, sGnn>>>(NN, x, h1);
    cudaEventRecord(evGemm1, sGnn);

    // main stream: count(+pos) -> scan -> fill(scatter) -> deg/dinv
    cudaMemsetAsync(counts, 0, NN * sizeof(int), 0);
    edge_count_pos<<<NB_EDGE, 256>>>(dst);
    scan_block<<<SCAN_B, SCAN_T>>>();
    scan_top<<<1, 64>>>();
    finalize_rowptr<<<NB_NODE, 256>>>();
    fill_csr<<<NB_EDGE, 256>>>(src, dst, ea);
    deg_dinv<<<NB_WARP, 256>>>();

    // aggregation 1 (+relu, + z-dot); needs h1, CSR, dinv, d_vg
    cudaStreamWaitEvent(0, evGemm1, 0);
    cudaStreamWaitEvent(0, evPrep, 0);
    gcn_agg1_z<<<NB_WARP, 256>>>(h1, g1b, z);

    // scalar aggregation 2 -> out (no dependency on MLP branch)
    gcn_agg2_out<<<NB_WARP, 256>>>(z, out);

    // join MLP stream into main so the captured graph is connected
    cudaStreamWaitEvent(0, evMlp, 0);
}

// round 17
// speedup vs baseline: 1.0925x; 1.0925x over previous
#include <cuda_runtime.h>
#include <cuda_fp16.h>
#include <cstdint>
#include <cstddef>

#define NN 50000
#define NE 800000
#define SCAN_T 1024
#define SCAN_B ((NN + SCAN_T - 1) / SCAN_T)   // 49

// ---------------- static device scratch ----------------
__device__ float d_dinv[NN];
__device__ int   d_counts[NN];
__device__ int   d_scanned[NN];
__device__ int   d_scanblk[SCAN_B];
__device__ int   d_rowptr[NN + 1];
__device__ int   d_epos[NE];
__device__ int   d_csr_src[NE];
__device__ float d_csr_w[NE];
__device__ float d_h1[NN * 64];
__device__ float d_z[NN];
__device__ float d_w2f[512];
__device__ float d_vg[64];
__device__ float d_cmlp;
__device__ float d_cgnn;
__device__ uint32_t d_w1h[4 * 8 * 2048];   // W1 fp16, fragment-major half2 words [bcol][kt][2048]
__device__ uint32_t d_g1h[8 * 1024];       // g1W fp16, fragment-major half2 words [kt][1024]

__device__ __forceinline__ uint32_t f2h2(float lo, float hi) {
    __half2 h = __floats2half2_rn(lo, hi);
    return *reinterpret_cast<uint32_t*>(&h);
}

// ---------------- precompute collapsed vectors ----------------
__global__ void prep_vecs(const float* __restrict__ W2, const float* __restrict__ g2W,
                          const float* __restrict__ b2, const float* __restrict__ g2b,
                          const float* __restrict__ Wf, const float* __restrict__ fb) {
    int t = threadIdx.x;   // 512 threads
    float s = 0.f;
#pragma unroll 8
    for (int c = 0; c < 64; c++) s += W2[t * 64 + c] * Wf[c];
    d_w2f[t] = s;
    if (t < 64) {
        float s2 = 0.f;
#pragma unroll 8
        for (int c = 0; c < 64; c++) s2 += g2W[t * 64 + c] * Wf[64 + c];
        d_vg[t] = s2;
    }
    if (t == 0) {
        float cm = 0.f, cg = 0.f;
        for (int c = 0; c < 64; c++) { cm += b2[c] * Wf[c]; cg += g2b[c] * Wf[64 + c]; }
        d_cmlp = cm;
        d_cgnn = cg + fb[0];
    }
}

// ---------------- fp16 fragment-major weight packing ----------------
// m16n8k16 B fragment: b0 = {B[K0+2t][n], B[K0+2t+1][n]}, b1 = same at K0+8.
// word j: j&1 -> +8 k-offset (b1), j>>1 -> odd nt of pair.
__global__ void prep_w1h(const float* __restrict__ W1) {
    int idx = blockIdx.x * blockDim.x + threadIdx.x;
    if (idx >= 4 * 8 * 2048) return;
    int tile = idx >> 11, w = idx & 2047;
    int bcol = tile >> 3, kt = tile & 7;
    int q = w >> 7, lane = (w >> 2) & 31, j = w & 3;
    int kstep = q >> 3, wn = (q >> 2) & 1, ntp = q & 3;
    int g = lane >> 2, t = lane & 3;
    int k = kt * 32 + kstep * 16 + 2 * t + (j & 1) * 8;
    int n = bcol * 128 + wn * 64 + (2 * ntp + (j >> 1)) * 8 + g;
    d_w1h[idx] = f2h2(W1[(size_t)k * 512 + n], W1[(size_t)(k + 1) * 512 + n]);
}

__global__ void prep_g1h(const float* __restrict__ B) {
    int idx = blockIdx.x * blockDim.x + threadIdx.x;
    if (idx >= 8 * 1024) return;
    int kt = idx >> 10, w = idx & 1023;
    int q = w >> 7, lane = (w >> 2) & 31, j = w & 3;
    int kstep = q >> 2, ntp = q & 3;
    int g = lane >> 2, t = lane & 3;
    int k = kt * 32 + kstep * 16 + 2 * t + (j & 1) * 8;
    int n = (2 * ntp + (j >> 1)) * 8 + g;
    d_g1h[idx] = f2h2(B[(size_t)k * 64 + n], B[(size_t)(k + 1) * 64 + n]);
}

// ---------------- graph preprocessing ----------------
__global__ void edge_count_pos(const int* __restrict__ dst) {
    int e = blockIdx.x * blockDim.x + threadIdx.x;
    if (e < NE) d_epos[e] = atomicAdd(&d_counts[dst[e]], 1);
}

__global__ void scan_block() {
    __shared__ int s[SCAN_T];
    int tid = threadIdx.x;
    int i = blockIdx.x * SCAN_T + tid;
    int v = (i < NN) ? d_counts[i] : 0;
    s[tid] = v;
    __syncthreads();
#pragma unroll
    for (int off = 1; off < SCAN_T; off <<= 1) {
        int t = (tid >= off) ? s[tid - off] : 0;
        __syncthreads();
        s[tid] += t;
        __syncthreads();
    }
    if (i < NN) d_scanned[i] = s[tid];
    if (tid == SCAN_T - 1) d_scanblk[blockIdx.x] = s[tid];
}

__global__ void scan_top() {
    __shared__ int s[64];
    int tid = threadIdx.x;
    int v = (tid < SCAN_B) ? d_scanblk[tid] : 0;
    s[tid] = v;
    __syncthreads();
#pragma unroll
    for (int off = 1; off < 64; off <<= 1) {
        int t = (tid >= off) ? s[tid - off] : 0;
        __syncthreads();
        s[tid] += t;
        __syncthreads();
    }
    if (tid < SCAN_B) d_scanblk[tid] = (tid == 0) ? 0 : s[tid - 1];
}

__global__ void finalize_rowptr() {
    int i = blockIdx.x * blockDim.x + threadIdx.x;
    if (i < NN) {
        d_rowptr[i + 1] = d_scanned[i] + d_scanblk[i >> 10];
        if (i == 0) d_rowptr[0] = 0;
    }
}

__global__ void fill_csr(const int* __restrict__ src, const int* __restrict__ dst,
                         const float* __restrict__ ew) {
    int e = blockIdx.x * blockDim.x + threadIdx.x;
    if (e < NE) {
        int pos = d_rowptr[dst[e]] + d_epos[e];
        d_csr_src[pos] = src[e];
        d_csr_w[pos] = ew[e];
    }
}

__global__ void deg_dinv() {
    int gw = (blockIdx.x * blockDim.x + threadIdx.x) >> 5;
    int lane = threadIdx.x & 31;
    if (gw >= NN) return;
    int beg = d_rowptr[gw];
    int end = d_rowptr[gw + 1];
    float s = 0.f;
    for (int j = beg + lane; j < end; j += 32) s += d_csr_w[j];
#pragma unroll
    for (int off = 16; off > 0; off >>= 1)
        s += __shfl_down_sync(0xFFFFFFFFu, s, off);
    if (lane == 0) d_dinv[gw] = rsqrtf(s + 1.0f);
}

// ---------------- GCN aggregation 1 + relu + z = g . vg ----------------
__global__ void gcn_agg1_z(const float* __restrict__ h, const float* __restrict__ bias,
                           float* __restrict__ z) {
    int gw = (blockIdx.x * blockDim.x + threadIdx.x) >> 5;
    int lane = threadIdx.x & 31;
    if (gw >= NN) return;
    int i = gw;
    float di = d_dinv[i];
    float a0 = di * h[(size_t)i * 64 + lane];
    float a1 = di * h[(size_t)i * 64 + 32 + lane];
    int beg = d_rowptr[i];
    int end = d_rowptr[i + 1];
    for (int jb = beg; jb < end; jb += 32) {
        int n = end - jb; if (n > 32) n = 32;
        int sj = 0; float wj = 0.f;
        if (lane < n) {
            sj = d_csr_src[jb + lane];
            wj = d_csr_w[jb + lane] * d_dinv[sj];
        }
        int k = 0;
        for (; k + 2 <= n; k += 2) {
            int s0 = __shfl_sync(0xFFFFFFFFu, sj, k);
            float w0 = __shfl_sync(0xFFFFFFFFu, wj, k);
            int s1 = __shfl_sync(0xFFFFFFFFu, sj, k + 1);
            float w1 = __shfl_sync(0xFFFFFFFFu, wj, k + 1);
            float v00 = h[(size_t)s0 * 64 + lane];
            float v01 = h[(size_t)s0 * 64 + 32 + lane];
            float v10 = h[(size_t)s1 * 64 + lane];
            float v11 = h[(size_t)s1 * 64 + 32 + lane];
            a0 += w0 * v00 + w1 * v10;
            a1 += w0 * v01 + w1 * v11;
        }
        if (k < n) {
            int s = __shfl_sync(0xFFFFFFFFu, sj, k);
            float w = __shfl_sync(0xFFFFFFFFu, wj, k);
            a0 += w * h[(size_t)s * 64 + lane];
            a1 += w * h[(size_t)s * 64 + 32 + lane];
        }
    }
    a0 = fmaxf(a0 * di + bias[lane], 0.0f);
    a1 = fmaxf(a1 * di + bias[32 + lane], 0.0f);
    float zi = a0 * d_vg[lane] + a1 * d_vg[32 + lane];
#pragma unroll
    for (int off = 16; off > 0; off >>= 1)
        zi += __shfl_down_sync(0xFFFFFFFFu, zi, off);
    if (lane == 0) z[i] = zi;
}

// ---------------- scalar aggregation 2, accumulate into out ----------------
__global__ void gcn_agg2_out(const float* __restrict__ z, float* __restrict__ out) {
    int gw = (blockIdx.x * blockDim.x + threadIdx.x) >> 5;
    int lane = threadIdx.x & 31;
    if (gw >= NN) return;
    int i = gw;
    float di = d_dinv[i];
    float acc = (lane == 0) ? di * z[i] : 0.0f;
    int beg = d_rowptr[i];
    int end = d_rowptr[i + 1];
    for (int j = beg + lane; j < end; j += 32) {
        int s = d_csr_src[j];
        acc += d_csr_w[j] * d_dinv[s] * z[s];
    }
#pragma unroll
    for (int off = 16; off > 0; off >>= 1)
        acc += __shfl_down_sync(0xFFFFFFFFu, acc, off);
    if (lane == 0) atomicAdd(&out[i], acc * di + d_cmlp + d_cgnn);
}

// ---------------- fp16 mma / cp.async helpers ----------------
__device__ __forceinline__ void mma_f16(float c[4], const uint32_t a[4],
                                        uint32_t b0, uint32_t b1) {
    asm volatile(
        "mma.sync.aligned.m16n8k16.row.col.f32.f16.f16.f32 "
        "{%0,%1,%2,%3},{%4,%5,%6,%7},{%8,%9},{%0,%1,%2,%3};\n"
        : "+f"(c[0]), "+f"(c[1]), "+f"(c[2]), "+f"(c[3])
        : "r"(a[0]), "r"(a[1]), "r"(a[2]), "r"(a[3]), "r"(b0), "r"(b1));
}

__device__ __forceinline__ uint32_t smem_u32(const void* p) {
    return (uint32_t)__cvta_generic_to_shared(p);
}
__device__ __forceinline__ void cp16(uint32_t dst, const void* src) {
    asm volatile("cp.async.cg.shared.global [%0], [%1], 16;" :: "r"(dst), "l"(src));
}
#define CP_COMMIT() asm volatile("cp.async.commit_group;" ::: "memory")
#define CP_WAIT(n)  asm volatile("cp.async.wait_group %0;" :: "n"(n) : "memory")

// A smem: fp32 row-major + XOR swizzle, word = row*32 + (k ^ ((row&7)<<2))
// B smem: fp16 fragment-major half2 words (packed offline), LDS.128 per nt-pair.

// ---------------- MLP GEMM (fp16): out[row] += relu(uf@W1+b1)[row,:] . w2f ----------------
// BM=128, BN=128, BK=32, 3-stage, 256 thr (4wm x 2wn, warp 32x64)
#define MLP_SMEM_BYTES ((3 * 4096 + 3 * 2048 + 128) * 4)

__global__ __launch_bounds__(256, 2) void mlp_gemm(
    int M, const float* __restrict__ A,
    const float* __restrict__ b1, float* __restrict__ out) {

    extern __shared__ float sm[];
    float*    sA = sm;                              // 3 x 4096 floats
    uint32_t* sB = (uint32_t*)(sm + 3 * 4096);      // 3 x 2048 half2-words
    float*    sRed = sm + 3 * 4096 + 3 * 2048;      // 128

    const int tid = threadIdx.x, brow = blockIdx.y, bcol = blockIdx.x;
    const int w = tid >> 5, lane = tid & 31, wm = w & 3, wn = w >> 2;
    const int g = lane >> 2, t = lane & 3;
    const int swA = g << 2;
    if (tid < 128) sRed[tid] = 0.f;

    const uint32_t sAu = smem_u32(sA), sBu = smem_u32(sB);
    const uint32_t* w1tile = d_w1h + (size_t)bcol * 8 * 2048;

    auto issue = [&](int kt, int s) {
#pragma unroll
        for (int i = 0; i < 4; i++) {
            int idx = tid + i * 256;
            int row = idx >> 3, c = idx & 7;
            int grow = brow * 128 + row; if (grow >= M) grow = M - 1;
            uint32_t dst = sAu + (uint32_t)(s * 4096 + row * 32 + ((c ^ (row & 7)) << 2)) * 4u;
            cp16(dst, &A[(size_t)grow * 256 + kt * 32 + c * 4]);
        }
#pragma unroll
        for (int i = 0; i < 2; i++) {
            int c2 = tid + i * 256;       // 16B chunk 0..511
            cp16(sBu + (uint32_t)(s * 2048 + c2 * 4) * 4u, &w1tile[kt * 2048 + c2 * 4]);
        }
        CP_COMMIT();
    };

    float acc[2][8][4] = {};

    issue(0, 0);
    issue(1, 1);
#pragma unroll
    for (int kt = 0; kt < 8; kt++) {
        if (kt == 7) { CP_WAIT(0); } else { CP_WAIT(1); }
        __syncthreads();
        const float* bA = sA + (kt % 3) * 4096;
        const uint4* bB4 = (const uint4*)(sB + (kt % 3) * 2048);
#pragma unroll
        for (int kstep = 0; kstep < 2; kstep++) {
            const int kb = kstep * 16;
            uint32_t a[2][4];
#pragma unroll
            for (int mt = 0; mt < 2; mt++) {
                int r0 = wm * 32 + mt * 16 + g;
                int r1 = r0 + 8;
                float2 f;
                f = *(const float2*)&bA[r0 * 32 + ((kb + 2 * t) ^ swA)];     a[mt][0] = f2h2(f.x, f.y);
                f = *(const float2*)&bA[r1 * 32 + ((kb + 2 * t) ^ swA)];     a[mt][1] = f2h2(f.x, f.y);
                f = *(const float2*)&bA[r0 * 32 + ((kb + 2 * t + 8) ^ swA)]; a[mt][2] = f2h2(f.x, f.y);
                f = *(const float2*)&bA[r1 * 32 + ((kb + 2 * t + 8) ^ swA)]; a[mt][3] = f2h2(f.x, f.y);
            }
#pragma unroll
            for (int ntp = 0; ntp < 4; ntp++) {
                uint4 bb = bB4[((kstep * 2 + wn) * 4 + ntp) * 32 + lane];
                mma_f16(acc[0][ntp * 2], a[0], bb.x, bb.y);
                mma_f16(acc[1][ntp * 2], a[1], bb.x, bb.y);
                mma_f16(acc[0][ntp * 2 + 1], a[0], bb.z, bb.w);
                mma_f16(acc[1][ntp * 2 + 1], a[1], bb.z, bb.w);
            }
        }
        if (kt < 6) issue(kt + 2, (kt + 2) % 3);
    }

    // epilogue: relu + dot with w2f
    float p[2][2] = {{0.f, 0.f}, {0.f, 0.f}};
#pragma unroll
    for (int nt = 0; nt < 8; nt++) {
        int gcol = bcol * 128 + wn * 64 + nt * 8 + t * 2;
        float bb0 = b1[gcol], bb1 = b1[gcol + 1];
        float w0 = d_w2f[gcol], w1 = d_w2f[gcol + 1];
#pragma unroll
        for (int mt = 0; mt < 2; mt++) {
            p[mt][0] += fmaxf(acc[mt][nt][0] + bb0, 0.f) * w0 + fmaxf(acc[mt][nt][1] + bb1, 0.f) * w1;
            p[mt][1] += fmaxf(acc[mt][nt][2] + bb0, 0.f) * w0 + fmaxf(acc[mt][nt][3] + bb1, 0.f) * w1;
        }
    }
#pragma unroll
    for (int off = 1; off <= 2; off <<= 1) {
        p[0][0] += __shfl_xor_sync(0xFFFFFFFFu, p[0][0], off);
        p[0][1] += __shfl_xor_sync(0xFFFFFFFFu, p[0][1], off);
        p[1][0] += __shfl_xor_sync(0xFFFFFFFFu, p[1][0], off);
        p[1][1] += __shfl_xor_sync(0xFFFFFFFFu, p[1][1], off);
    }
    if (t == 0) {
#pragma unroll
        for (int mt = 0; mt < 2; mt++) {
            int r0 = wm * 32 + mt * 16 + g;
            atomicAdd(&sRed[r0], p[mt][0]);
            atomicAdd(&sRed[r0 + 8], p[mt][1]);
        }
    }
    __syncthreads();
    if (tid < 128) {
        int grow = brow * 128 + tid;
        if (grow < M) atomicAdd(&out[grow], sRed[tid]);
    }
}

// ---------------- GCN1 transform (fp16): h1 = x @ g1W ----------------
// 128 thr (4 warps), warp tile 32x64, BM=128, BN=64, BK=32, 3-stage.
#define G1_SMEM_BYTES ((3 * 4096 + 3 * 1024) * 4)

__global__ __launch_bounds__(128, 2) void gcn1_gemm(
    int M, const float* __restrict__ A, float* __restrict__ C) {

    extern __shared__ float sm[];
    float*    sA = sm;                              // 3 x 4096 floats
    uint32_t* sB = (uint32_t*)(sm + 3 * 4096);      // 3 x 1024 half2-words

    const int tid = threadIdx.x, brow = blockIdx.x;
    const int wm = tid >> 5, lane = tid & 31;
    const int g = lane >> 2, t = lane & 3;
    const int swA = g << 2;

    const uint32_t sAu = smem_u32(sA), sBu = smem_u32(sB);

    auto issue = [&](int kt, int s) {
#pragma unroll
        for (int i = 0; i < 8; i++) {
            int idx = tid + i * 128;
            int row = idx >> 3, c = idx & 7;
            int grow = brow * 128 + row; if (grow >= M) grow = M - 1;
            uint32_t dst = sAu + (uint32_t)(s * 4096 + row * 32 + ((c ^ (row & 7)) << 2)) * 4u;
            cp16(dst, &A[(size_t)grow * 256 + kt * 32 + c * 4]);
        }
#pragma unroll
        for (int i = 0; i < 2; i++) {
            int c2 = tid + i * 128;       // 16B chunk 0..255
            cp16(sBu + (uint32_t)(s * 1024 + c2 * 4) * 4u, &d_g1h[kt * 1024 + c2 * 4]);
        }
        CP_COMMIT();
    };

    float acc[2][8][4] = {};

    issue(0, 0);
    issue(1, 1);
#pragma unroll
    for (int kt = 0; kt < 8; kt++) {
        if (kt == 7) { CP_WAIT(0); } else { CP_WAIT(1); }
        __syncthreads();
        const float* bA = sA + (kt % 3) * 4096;
        const uint4* bB4 = (const uint4*)(sB + (kt % 3) * 1024);
#pragma unroll
        for (int kstep = 0; kstep < 2; kstep++) {
            const int kb = kstep * 16;
            uint32_t a[2][4];
#pragma unroll
            for (int mt = 0; mt < 2; mt++) {
                int r0 = wm * 32 + mt * 16 + g;
                int r1 = r0 + 8;
                float2 f;
                f = *(const float2*)&bA[r0 * 32 + ((kb + 2 * t) ^ swA)];     a[mt][0] = f2h2(f.x, f.y);
                f = *(const float2*)&bA[r1 * 32 + ((kb + 2 * t) ^ swA)];     a[mt][1] = f2h2(f.x, f.y);
                f = *(const float2*)&bA[r0 * 32 + ((kb + 2 * t + 8) ^ swA)]; a[mt][2] = f2h2(f.x, f.y);
                f = *(const float2*)&bA[r1 * 32 + ((kb + 2 * t + 8) ^ swA)]; a[mt][3] = f2h2(f.x, f.y);
            }
#pragma unroll
            for (int ntp = 0; ntp < 4; ntp++) {
                uint4 bb = bB4[(kstep * 4 + ntp) * 32 + lane];
                mma_f16(acc[0][ntp * 2], a[0], bb.x, bb.y);
                mma_f16(acc[1][ntp * 2], a[1], bb.x, bb.y);
                mma_f16(acc[0][ntp * 2 + 1], a[0], bb.z, bb.w);
                mma_f16(acc[1][ntp * 2 + 1], a[1], bb.z, bb.w);
            }
        }
        if (kt < 6) issue(kt + 2, (kt + 2) % 3);
    }

#pragma unroll
    for (int mt = 0; mt < 2; mt++) {
#pragma unroll
        for (int nt = 0; nt < 8; nt++) {
            int gcol = nt * 8 + t * 2;
            int grow0 = brow * 128 + wm * 32 + mt * 16 + g;
            if (grow0 < M)
                *(float2*)&C[(size_t)grow0 * 64 + gcol] = make_float2(acc[mt][nt][0], acc[mt][nt][1]);
            if (grow0 + 8 < M)
                *(float2*)&C[(size_t)(grow0 + 8) * 64 + gcol] = make_float2(acc[mt][nt][2], acc[mt][nt][3]);
        }
    }
}

// ---------------- launch ----------------
extern "C" void kernel_launch(void* const* d_in, const int* in_sizes, int n_in,
                              void* d_out, int out_size) {
    const float* x     = (const float*)d_in[0];
    const int*   ei    = (const int*)d_in[1];
    const float* ea    = (const float*)d_in[2];
    const float* uf    = (const float*)d_in[3];
    const float* g1W   = (const float*)d_in[4];
    const float* g1b   = (const float*)d_in[5];
    const float* g2W   = (const float*)d_in[6];
    const float* g2b   = (const float*)d_in[7];
    const float* fc1W  = (const float*)d_in[8];
    const float* fc1b  = (const float*)d_in[9];
    const float* fc2W  = (const float*)d_in[10];
    const float* fc2b  = (const float*)d_in[11];
    const float* fcfW  = (const float*)d_in[12];
    const float* fcfb  = (const float*)d_in[13];
    float* out = (float*)d_out;

    const int* src = ei;
    const int* dst = ei + NE;

    void* p;
    cudaGetSymbolAddress(&p, d_h1);     float* h1     = (float*)p;
    cudaGetSymbolAddress(&p, d_z);      float* z      = (float*)p;
    cudaGetSymbolAddress(&p, d_counts); int*   counts = (int*)p;

    const int NB_NODE = (NN + 255) / 256;
    const int NB_EDGE = (NE + 255) / 256;
    const int NB_WARP = (NN * 32 + 255) / 256;
    const int MB = (NN + 127) / 128;   // 391

    static cudaStream_t sMlp = nullptr, sGnn = nullptr;
    static cudaEvent_t evFork = nullptr, evMlp = nullptr, evGemm1 = nullptr,
                       evPrep = nullptr, evOut = nullptr;
    static bool inited = false;
    if (!inited) {
        cudaStreamCreateWithFlags(&sMlp, cudaStreamNonBlocking);
        cudaStreamCreateWithFlags(&sGnn, cudaStreamNonBlocking);
        cudaEventCreateWithFlags(&evFork, cudaEventDisableTiming);
        cudaEventCreateWithFlags(&evMlp, cudaEventDisableTiming);
        cudaEventCreateWithFlags(&evGemm1, cudaEventDisableTiming);
        cudaEventCreateWithFlags(&evPrep, cudaEventDisableTiming);
        cudaEventCreateWithFlags(&evOut, cudaEventDisableTiming);
        cudaFuncSetAttribute(mlp_gemm, cudaFuncAttributeMaxDynamicSharedMemorySize,
                             MLP_SMEM_BYTES);
        cudaFuncSetAttribute(gcn1_gemm, cudaFuncAttributeMaxDynamicSharedMemorySize,
                             G1_SMEM_BYTES);
        inited = true;
    }

    cudaEventRecord(evFork, 0);
    cudaStreamWaitEvent(sGnn, evFork, 0);
    cudaStreamWaitEvent(sMlp, evFork, 0);

    // out accumulator: zero; both branches atomicAdd into it
    cudaMemsetAsync(out, 0, NN * sizeof(float), 0);
    cudaEventRecord(evOut, 0);
    cudaStreamWaitEvent(sMlp, evOut, 0);

    // MLP branch on sMlp
    prep_vecs<<<1, 512, 0, sMlp>>>(fc2W, g2W, fc2b, g2b, fcfW, fcfb);
    cudaEventRecord(evPrep, sMlp);
    prep_w1h<<<(4 * 8 * 2048 + 255) / 256, 256, 0, sMlp>>>(fc1W);
    mlp_gemm<<<dim3(4, MB), 256, MLP_SMEM_BYTES, sMlp>>>(NN, uf, fc1b, out);
    cudaEventRecord(evMlp, sMlp);

    // GNN transform on sGnn
    prep_g1h<<<(8 * 1024 + 255) / 256, 256, 0, sGnn>>>(g1W);
    gcn1_gemm<<<MB, 128, G1_SMEM_BYTES, sGnn>>>(NN, x, h1);
    cudaEventRecord(evGemm1, sGnn);

    // main stream: count(+pos) -> scan -> fill(scatter) -> deg/dinv
    cudaMemsetAsync(counts, 0, NN * sizeof(int), 0);
    edge_count_pos<<<NB_EDGE, 256>>>(dst);
    scan_block<<<SCAN_B, SCAN_T>>>();
    scan_top<<<1, 64>>>();
    finalize_rowptr<<<NB_NODE, 256>>>();
    fill_csr<<<NB_EDGE, 256>>>(src, dst, ea);
    deg_dinv<<<NB_WARP, 256>>>();

    // aggregation 1 (+relu, + z-dot); needs h1, CSR, dinv, d_vg
    cudaStreamWaitEvent(0, evGemm1, 0);
    cudaStreamWaitEvent(0, evPrep, 0);
    gcn_agg1_z<<<NB_WARP, 256>>>(h1, g1b, z);

    // scalar aggregation 2 -> out (no dependency on MLP branch)
    gcn_agg2_out<<<NB_WARP, 256>>>(z, out);

    // join MLP stream into main
    cudaStreamWaitEvent(0, evMlp, 0);
}